// round 13
// baseline (speedup 1.0000x reference)
#include <cuda_runtime.h>
#include <math.h>
#include <stdint.h>

#define NN   100000
#define NE   1600000
#define INC  256
#define HIDD 128
#define HEADS 4
#define CHEAD 32
#define BN_EPS 1e-5f
#define NEG_SLOPE 0.2f
#define SCANB 1024
#define NBLK  ((NN + SCANB - 1) / SCANB)   // 98

// ---------------- scratch (device globals: no allocs allowed) ----------------
__device__ float    g_h   [(size_t)NN*HIDD];   // x @ W_gat
__device__ float    g_out1[(size_t)NN*HIDD];   // GAT aggregation (pre BN1)
__device__ uint32_t g_zhi [(size_t)NN*64];     // z=(1+eps)h1+agg, bf16 hi pairs
__device__ uint32_t g_zlo [(size_t)NN*64];     // bf16 lo pairs
__device__ uint32_t g_B1hi[INC*64],  g_B1lo[INC*64];    // W_gat bf16 col-pairs
__device__ uint32_t g_B2hi[HIDD*64], g_B2lo[HIDD*64];   // lin_W
__device__ float g_asrc[NN*HEADS];
__device__ float g_adst[NN*HEADS];
__device__ float g_sum [HIDD];
__device__ float g_sumsq[HIDD];
__device__ float g_scale[HIDD];
__device__ float g_shift[HIDD];
__device__ int   g_src[NE];
__device__ int   g_dst[NE];
__device__ int   g_esrc[NE];                // CSR: src ids grouped by dst
__device__ int   g_rowptr[NN+1];
__device__ int   g_deg[NN];
__device__ int   g_woff[NN];
__device__ int   g_bsum[NBLK];
__device__ int   g_boff[NBLK];
__device__ int   g_is64;

// ---------------- helpers ----------------
__device__ __forceinline__ void redAdd1(float* addr, float v) {
    asm volatile("red.global.add.f32 [%0], %1;" :: "l"(addr), "f"(v) : "memory");
}
__device__ __forceinline__ float lrelu(float x) { return x > 0.0f ? x : NEG_SLOPE * x; }
__device__ __forceinline__ float elu(float x)   { return x > 0.0f ? x : expm1f(x); }

__device__ __forceinline__ uint32_t bf16pack(float x1, float x0) {
    uint32_t r;
    asm("cvt.rn.bf16x2.f32 %0, %1, %2;" : "=r"(r) : "f"(x1), "f"(x0));
    return r;
}
__device__ __forceinline__ void hiLo(float x0, float x1, uint32_t& h, uint32_t& l) {
    h = bf16pack(x1, x0);
    float r0 = x0 - __uint_as_float(h << 16);
    float r1 = x1 - __uint_as_float(h & 0xffff0000u);
    l = bf16pack(r1, r0);
}

#define LDM_X4(r, addr)                                                        \
    asm volatile("ldmatrix.sync.aligned.m8n8.x4.shared.b16 {%0,%1,%2,%3}, [%4];" \
        : "=r"((r)[0]), "=r"((r)[1]), "=r"((r)[2]), "=r"((r)[3]) : "r"(addr))
#define LDM_X4T(r, addr)                                                       \
    asm volatile("ldmatrix.sync.aligned.m8n8.x4.trans.shared.b16 {%0,%1,%2,%3}, [%4];" \
        : "=r"((r)[0]), "=r"((r)[1]), "=r"((r)[2]), "=r"((r)[3]) : "r"(addr))
#define MMA16(d, a, b0, b1)                                                    \
    asm volatile("mma.sync.aligned.m16n8k16.row.col.f32.bf16.bf16.f32 "        \
        "{%0,%1,%2,%3}, {%4,%5,%6,%7}, {%8,%9}, {%0,%1,%2,%3};"                \
        : "+f"((d)[0]), "+f"((d)[1]), "+f"((d)[2]), "+f"((d)[3])               \
        : "r"((a)[0]), "r"((a)[1]), "r"((a)[2]), "r"((a)[3]), "r"(b0), "r"(b1))

// ---------------- init ----------------
__global__ void k_init() {
    int i = blockIdx.x * blockDim.x + threadIdx.x;
    if (i < NN) { g_deg[i] = 0; g_woff[i] = 0; }
    if (i < HIDD) { g_sum[i] = 0.0f; g_sumsq[i] = 0.0f; }
}

__global__ void k_detect(const long long* __restrict__ ei) {
    __shared__ int ok;
    if (threadIdx.x == 0) ok = 1;
    __syncthreads();
    for (int i = threadIdx.x; i < 1024; i += blockDim.x) {
        long long v = ei[i];
        if (v < 0 || v >= NN) atomicExch(&ok, 0);
    }
    __syncthreads();
    if (threadIdx.x == 0) g_is64 = ok;
}

__global__ void k_edgecvt(const void* __restrict__ eiv) {
    int i = blockIdx.x * blockDim.x + threadIdx.x;
    if (i >= NE) return;
    int s, d;
    if (g_is64) {
        const long long* p = (const long long*)eiv;
        s = (int)p[i]; d = (int)p[NE + i];
    } else {
        const int* p = (const int*)eiv;
        s = p[i]; d = p[NE + i];
    }
    g_src[i] = s;
    g_dst[i] = d;
    atomicAdd(&g_deg[d], 1);
}

// ---------------- prefix scan ----------------
__global__ void k_scan1() {
    __shared__ int sh[SCANB];
    int tid = threadIdx.x;
    int i = blockIdx.x * SCANB + tid;
    int v = (i < NN) ? g_deg[i] : 0;
    sh[tid] = v;
    __syncthreads();
    for (int off = 1; off < SCANB; off <<= 1) {
        int t = (tid >= off) ? sh[tid - off] : 0;
        __syncthreads();
        sh[tid] += t;
        __syncthreads();
    }
    if (i < NN) g_rowptr[i + 1] = sh[tid];
    if (tid == SCANB - 1) g_bsum[blockIdx.x] = sh[tid];
}

// 128-thread shfl scan over NBLK block sums -> exclusive offsets
__global__ void k_scan2() {
    __shared__ int wsum[4];
    int t = threadIdx.x, lane = t & 31, w = t >> 5;
    int v = (t < NBLK) ? g_bsum[t] : 0;
    int x = v;
#pragma unroll
    for (int off = 1; off < 32; off <<= 1) {
        int y = __shfl_up_sync(0xffffffffu, x, off);
        if (lane >= off) x += y;
    }
    if (lane == 31) wsum[w] = x;
    __syncthreads();
    int wpre = 0;
#pragma unroll
    for (int k = 0; k < 4; k++) if (k < w) wpre += wsum[k];
    if (t < NBLK) g_boff[t] = wpre + x - v;   // exclusive
}

__global__ void k_scan3() {
    int i = blockIdx.x * blockDim.x + threadIdx.x;
    if (i == 0) g_rowptr[0] = 0;
    if (i < NN) g_rowptr[i + 1] += g_boff[i >> 10];
}
__global__ void k_scatter() {
    int e = blockIdx.x * blockDim.x + threadIdx.x;
    if (e >= NE) return;
    int d = g_dst[e];
    int pos = g_rowptr[d] + atomicAdd(&g_woff[d], 1);
    g_esrc[pos] = g_src[e];
}

// ---------------- preconvert weights to bf16 hi/lo (col-pair packed) --------
__global__ void k_cvtW(const float* __restrict__ Wg, const float* __restrict__ Wl) {
    int i = blockIdx.x * blockDim.x + threadIdx.x;
    if (i < INC * 64) {
        float2 v = *(const float2*)(Wg + (size_t)i * 2);
        uint32_t h, l; hiLo(v.x, v.y, h, l);
        g_B1hi[i] = h; g_B1lo[i] = l;
    } else if (i < INC * 64 + HIDD * 64) {
        int j = i - INC * 64;
        float2 v = *(const float2*)(Wl + (size_t)j * 2);
        uint32_t h, l; hiLo(v.x, v.y, h, l);
        g_B2hi[j] = h; g_B2lo[j] = l;
    }
}

// -------- GEMM1: g_h = x @ W_gat (bf16x3) + attention logits epilogue -------
__global__ __launch_bounds__(256, 2) void k_gemm1(
    const float* __restrict__ A,
    const float* __restrict__ att_s, const float* __restrict__ att_d)
{
    __shared__ uint32_t sAhi[128][20], sAlo[128][20];
    __shared__ uint32_t sBhi[32][68],  sBlo[32][68];
    __shared__ float    sAS[128][4],   sAD[128][4];

    int t = threadIdx.x, lane = t & 31, wid = t >> 5;
    int g = lane >> 2, tq = lane & 3;
    int wm = wid >> 1, wn = wid & 1;
    int blockM = blockIdx.x * 128;

    if (t < 128) {
#pragma unroll
        for (int hd = 0; hd < 4; hd++) { sAS[t][hd] = 0.f; sAD[t][hd] = 0.f; }
    }

    unsigned aHiB = (unsigned)__cvta_generic_to_shared(&sAhi[0][0]);
    unsigned aLoB = (unsigned)__cvta_generic_to_shared(&sAlo[0][0]);
    unsigned bHiB = (unsigned)__cvta_generic_to_shared(&sBhi[0][0]);
    unsigned bLoB = (unsigned)__cvta_generic_to_shared(&sBlo[0][0]);

    int la_row = (lane & 7) + 8 * ((lane >> 3) & 1);
    int la_k   = ((lane >> 4) & 1) * 4;
    int lb_k   = (lane & 7) + 8 * ((lane >> 3) & 1);
    int lb_c   = ((lane >> 4) & 1) * 4;

    float acc[2][8][4];
#pragma unroll
    for (int m = 0; m < 2; m++)
#pragma unroll
        for (int j = 0; j < 8; j++)
#pragma unroll
            for (int c = 0; c < 4; c++) acc[m][j][c] = 0.0f;

    for (int kt = 0; kt < INC / 32; kt++) {
#pragma unroll
        for (int i = 0; i < 4; i++) {
            int li  = i * 256 + t;
            int row = li >> 3, kidx = li & 7;
            int grow = blockM + row;
            float4 v = make_float4(0.f, 0.f, 0.f, 0.f);
            if (grow < NN)
                v = *(const float4*)(A + (size_t)grow * INC + kt * 32 + kidx * 4);
            uint32_t h0, l0, h1, l1;
            hiLo(v.x, v.y, h0, l0);
            hiLo(v.z, v.w, h1, l1);
            sAhi[row][kidx * 2] = h0; sAhi[row][kidx * 2 + 1] = h1;
            sAlo[row][kidx * 2] = l0; sAlo[row][kidx * 2 + 1] = l1;
        }
#pragma unroll
        for (int i = 0; i < 2; i++) {
            int li = i * 256 + t;
            int k  = li >> 4, c4 = (li & 15) * 4;
            size_t gi = (size_t)(kt * 32 + k) * 64 + c4;
            *(uint4*)&sBhi[k][c4] = *(const uint4*)(g_B1hi + gi);
            *(uint4*)&sBlo[k][c4] = *(const uint4*)(g_B1lo + gi);
        }
        __syncthreads();

#pragma unroll
        for (int ks = 0; ks < 2; ks++) {
            int Kw = ks * 8;
            uint32_t ahi[2][4], alo[2][4];
#pragma unroll
            for (int m = 0; m < 2; m++) {
                int R0 = wm * 32 + m * 16;
                unsigned off = ((R0 + la_row) * 20 + Kw + la_k) * 4;
                LDM_X4(ahi[m], aHiB + off);
                LDM_X4(alo[m], aLoB + off);
            }
#pragma unroll
            for (int jj = 0; jj < 4; jj++) {
                int C0 = wn * 64 + jj * 16;
                unsigned off = ((ks * 16 + lb_k) * 68 + C0 / 2 + lb_c) * 4;
                uint32_t bh[4], bl[4];
                LDM_X4T(bh, bHiB + off);
                LDM_X4T(bl, bLoB + off);
#pragma unroll
                for (int m = 0; m < 2; m++) {
                    MMA16(acc[m][2 * jj],     ahi[m], bh[0], bh[1]);
                    MMA16(acc[m][2 * jj],     ahi[m], bl[0], bl[1]);
                    MMA16(acc[m][2 * jj],     alo[m], bh[0], bh[1]);
                    MMA16(acc[m][2 * jj + 1], ahi[m], bh[2], bh[3]);
                    MMA16(acc[m][2 * jj + 1], ahi[m], bl[2], bl[3]);
                    MMA16(acc[m][2 * jj + 1], alo[m], bh[2], bh[3]);
                }
            }
        }
        __syncthreads();
    }

    float ps[4][2], pd[4][2];
#pragma unroll
    for (int r = 0; r < 4; r++) { ps[r][0] = ps[r][1] = 0.f; pd[r][0] = pd[r][1] = 0.f; }

#pragma unroll
    for (int m = 0; m < 2; m++) {
#pragma unroll
        for (int j = 0; j < 8; j++) {
            int row = blockM + wm * 32 + m * 16 + g;
            int col = wn * 64 + j * 8 + tq * 2;
            if (row < NN)
                *(float2*)(g_h + (size_t)row * HIDD + col) =
                    make_float2(acc[m][j][0], acc[m][j][1]);
            if (row + 8 < NN)
                *(float2*)(g_h + (size_t)(row + 8) * HIDD + col) =
                    make_float2(acc[m][j][2], acc[m][j][3]);
            float as0 = __ldg(att_s + col), as1 = __ldg(att_s + col + 1);
            float ad0 = __ldg(att_d + col), ad1 = __ldg(att_d + col + 1);
            int hh = j >> 2;
            ps[m * 2 + 0][hh] += acc[m][j][0] * as0 + acc[m][j][1] * as1;
            pd[m * 2 + 0][hh] += acc[m][j][0] * ad0 + acc[m][j][1] * ad1;
            ps[m * 2 + 1][hh] += acc[m][j][2] * as0 + acc[m][j][3] * as1;
            pd[m * 2 + 1][hh] += acc[m][j][2] * ad0 + acc[m][j][3] * ad1;
        }
    }
#pragma unroll
    for (int m = 0; m < 2; m++) {
#pragma unroll
        for (int r = 0; r < 2; r++) {
            int rloc = wm * 32 + m * 16 + g + r * 8;
#pragma unroll
            for (int hh = 0; hh < 2; hh++) {
                atomicAdd(&sAS[rloc][wn * 2 + hh], ps[m * 2 + r][hh]);
                atomicAdd(&sAD[rloc][wn * 2 + hh], pd[m * 2 + r][hh]);
            }
        }
    }
    __syncthreads();
    if (t < 128) {
        int row = blockM + t;
        if (row < NN) {
            *(float4*)(g_asrc + row * 4) = *(const float4*)&sAS[t][0];
            *(float4*)(g_adst + row * 4) = *(const float4*)&sAD[t][0];
        }
    }
}

// ---------------- GEMM2: out = z @ lin_W, + BN2 stats (bf16x3) --------------
__global__ __launch_bounds__(256, 2) void k_gemm2(float* __restrict__ C) {
    __shared__ uint32_t sAhi[128][20], sAlo[128][20];
    __shared__ uint32_t sBhi[32][68],  sBlo[32][68];

    int t = threadIdx.x, lane = t & 31, wid = t >> 5;
    int g = lane >> 2, tq = lane & 3;
    int wm = wid >> 1, wn = wid & 1;
    int blockM = blockIdx.x * 128;

    unsigned aHiB = (unsigned)__cvta_generic_to_shared(&sAhi[0][0]);
    unsigned aLoB = (unsigned)__cvta_generic_to_shared(&sAlo[0][0]);
    unsigned bHiB = (unsigned)__cvta_generic_to_shared(&sBhi[0][0]);
    unsigned bLoB = (unsigned)__cvta_generic_to_shared(&sBlo[0][0]);

    int la_row = (lane & 7) + 8 * ((lane >> 3) & 1);
    int la_k   = ((lane >> 4) & 1) * 4;
    int lb_k   = (lane & 7) + 8 * ((lane >> 3) & 1);
    int lb_c   = ((lane >> 4) & 1) * 4;

    float acc[2][8][4];
#pragma unroll
    for (int m = 0; m < 2; m++)
#pragma unroll
        for (int j = 0; j < 8; j++)
#pragma unroll
            for (int c = 0; c < 4; c++) acc[m][j][c] = 0.0f;

    for (int kt = 0; kt < HIDD / 32; kt++) {
#pragma unroll
        for (int i = 0; i < 2; i++) {
            int li  = i * 256 + t;
            int row = li >> 2, wq = (li & 3) * 4;
            int grow = blockM + row;
            uint4 vh = make_uint4(0, 0, 0, 0), vl = make_uint4(0, 0, 0, 0);
            if (grow < NN) {
                size_t gi = (size_t)grow * 64 + kt * 16 + wq;
                vh = *(const uint4*)(g_zhi + gi);
                vl = *(const uint4*)(g_zlo + gi);
            }
            *(uint4*)&sAhi[row][wq] = vh;
            *(uint4*)&sAlo[row][wq] = vl;
        }
#pragma unroll
        for (int i = 0; i < 2; i++) {
            int li = i * 256 + t;
            int k  = li >> 4, c4 = (li & 15) * 4;
            size_t gi = (size_t)(kt * 32 + k) * 64 + c4;
            *(uint4*)&sBhi[k][c4] = *(const uint4*)(g_B2hi + gi);
            *(uint4*)&sBlo[k][c4] = *(const uint4*)(g_B2lo + gi);
        }
        __syncthreads();

#pragma unroll
        for (int ks = 0; ks < 2; ks++) {
            int Kw = ks * 8;
            uint32_t ahi[2][4], alo[2][4];
#pragma unroll
            for (int m = 0; m < 2; m++) {
                int R0 = wm * 32 + m * 16;
                unsigned off = ((R0 + la_row) * 20 + Kw + la_k) * 4;
                LDM_X4(ahi[m], aHiB + off);
                LDM_X4(alo[m], aLoB + off);
            }
#pragma unroll
            for (int jj = 0; jj < 4; jj++) {
                int C0 = wn * 64 + jj * 16;
                unsigned off = ((ks * 16 + lb_k) * 68 + C0 / 2 + lb_c) * 4;
                uint32_t bh[4], bl[4];
                LDM_X4T(bh, bHiB + off);
                LDM_X4T(bl, bLoB + off);
#pragma unroll
                for (int m = 0; m < 2; m++) {
                    MMA16(acc[m][2 * jj],     ahi[m], bh[0], bh[1]);
                    MMA16(acc[m][2 * jj],     ahi[m], bl[0], bl[1]);
                    MMA16(acc[m][2 * jj],     alo[m], bh[0], bh[1]);
                    MMA16(acc[m][2 * jj + 1], ahi[m], bh[2], bh[3]);
                    MMA16(acc[m][2 * jj + 1], ahi[m], bl[2], bl[3]);
                    MMA16(acc[m][2 * jj + 1], alo[m], bh[2], bh[3]);
                }
            }
        }
        __syncthreads();
    }

#pragma unroll
    for (int m = 0; m < 2; m++) {
#pragma unroll
        for (int j = 0; j < 8; j++) {
            int row = blockM + wm * 32 + m * 16 + g;
            int col = wn * 64 + j * 8 + tq * 2;
            if (row < NN)
                *(float2*)(C + (size_t)row * HIDD + col) =
                    make_float2(acc[m][j][0], acc[m][j][1]);
            if (row + 8 < NN)
                *(float2*)(C + (size_t)(row + 8) * HIDD + col) =
                    make_float2(acc[m][j][2], acc[m][j][3]);
        }
    }

#pragma unroll
    for (int j = 0; j < 8; j++) {
        float s0 = 0.f, q0 = 0.f, s1 = 0.f, q1 = 0.f;
#pragma unroll
        for (int m = 0; m < 2; m++) {
            float v0 = acc[m][j][0], v1 = acc[m][j][1];
            float v2 = acc[m][j][2], v3 = acc[m][j][3];
            s0 += v0 + v2; q0 += v0 * v0 + v2 * v2;
            s1 += v1 + v3; q1 += v1 * v1 + v3 * v3;
        }
#pragma unroll
        for (int off = 4; off < 32; off <<= 1) {
            s0 += __shfl_xor_sync(0xffffffffu, s0, off);
            q0 += __shfl_xor_sync(0xffffffffu, q0, off);
            s1 += __shfl_xor_sync(0xffffffffu, s1, off);
            q1 += __shfl_xor_sync(0xffffffffu, q1, off);
        }
        if (g == 0) {
            int cn = wn * 64 + j * 8 + tq * 2;
            redAdd1(g_sum + cn, s0);     redAdd1(g_sumsq + cn, q0);
            redAdd1(g_sum + cn + 1, s1); redAdd1(g_sumsq + cn + 1, q1);
        }
    }
}

// -------- GAT fused softmax+aggregate (warp/dst) + smem BN1 stats — R5 ------
__global__ __launch_bounds__(256) void k_gat_csr() {
    __shared__ float ssum[HIDD], ssq[HIDD];
    int t = threadIdx.x;
    if (t < HIDD) { ssum[t] = 0.f; ssq[t] = 0.f; }
    __syncthreads();

    int gw   = (blockIdx.x * blockDim.x + t) >> 5;
    int lane = t & 31;
    float4 acc = make_float4(0.f, 0.f, 0.f, 0.f);

    if (gw < NN) {
        int d  = gw;
        int r0 = g_rowptr[d], r1 = g_rowptr[d + 1];
        if (r0 < r1) {
            float4 ad = *(const float4*)(g_adst + d * 4);
            float4 m = make_float4(-INFINITY, -INFINITY, -INFINITY, -INFINITY);
            for (int i = r0 + lane; i < r1; i += 32) {
                int s = g_esrc[i];
                float4 a = *(const float4*)(g_asrc + s * 4);
                m.x = fmaxf(m.x, lrelu(a.x + ad.x));
                m.y = fmaxf(m.y, lrelu(a.y + ad.y));
                m.z = fmaxf(m.z, lrelu(a.z + ad.z));
                m.w = fmaxf(m.w, lrelu(a.w + ad.w));
            }
#pragma unroll
            for (int off = 16; off; off >>= 1) {
                m.x = fmaxf(m.x, __shfl_xor_sync(0xffffffffu, m.x, off));
                m.y = fmaxf(m.y, __shfl_xor_sync(0xffffffffu, m.y, off));
                m.z = fmaxf(m.z, __shfl_xor_sync(0xffffffffu, m.z, off));
                m.w = fmaxf(m.w, __shfl_xor_sync(0xffffffffu, m.w, off));
            }
            int head = lane >> 3;
            float mh  = (head == 0) ? m.x  : (head == 1) ? m.y  : (head == 2) ? m.z  : m.w;
            float adh = (head == 0) ? ad.x : (head == 1) ? ad.y : (head == 2) ? ad.z : ad.w;
            float den = 0.f;
            for (int i = r0; i < r1; i++) {
                int s = g_esrc[i];
                float ah = __ldg(g_asrc + s * 4 + head);
                float num = expf(lrelu(ah + adh) - mh);
                den += num;
                float4 hv = *(const float4*)(g_h + (size_t)s * HIDD + lane * 4);
                acc.x += num * hv.x; acc.y += num * hv.y;
                acc.z += num * hv.z; acc.w += num * hv.w;
            }
            float inv = 1.0f / den;
            acc.x *= inv; acc.y *= inv; acc.z *= inv; acc.w *= inv;
        }
        *(float4*)(g_out1 + (size_t)gw * HIDD + lane * 4) = acc;
        atomicAdd(&ssum[lane * 4 + 0], acc.x); atomicAdd(&ssq[lane * 4 + 0], acc.x * acc.x);
        atomicAdd(&ssum[lane * 4 + 1], acc.y); atomicAdd(&ssq[lane * 4 + 1], acc.y * acc.y);
        atomicAdd(&ssum[lane * 4 + 2], acc.z); atomicAdd(&ssq[lane * 4 + 2], acc.z * acc.z);
        atomicAdd(&ssum[lane * 4 + 3], acc.w); atomicAdd(&ssq[lane * 4 + 3], acc.w * acc.w);
    }
    __syncthreads();
    if (t < HIDD) {
        redAdd1(g_sum + t, ssum[t]);
        redAdd1(g_sumsq + t, ssq[t]);
    }
}

// -------- GIN fused with BN1 apply + ELU:
// h1[r] = elu(out1[r]*scale + shift) computed on the fly per gathered row;
// z = (1+eps)*h1[d] + sum_src h1[src], emit bf16 hi/lo ----------------------
__global__ __launch_bounds__(256) void k_gin_z(const float* __restrict__ epsPtr) {
    int gw   = (blockIdx.x * blockDim.x + threadIdx.x) >> 5;
    int lane = threadIdx.x & 31;
    if (gw >= NN) return;
    int d  = gw;
    int r0 = g_rowptr[d], r1 = g_rowptr[d + 1];
    float ke = 1.0f + __ldg(epsPtr);

    float4 sc = *(const float4*)(g_scale + lane * 4);
    float4 sh = *(const float4*)(g_shift + lane * 4);

    float4 v = *(const float4*)(g_out1 + (size_t)d * HIDD + lane * 4);
    float4 acc;
    acc.x = ke * elu(v.x * sc.x + sh.x);
    acc.y = ke * elu(v.y * sc.y + sh.y);
    acc.z = ke * elu(v.z * sc.z + sh.z);
    acc.w = ke * elu(v.w * sc.w + sh.w);

    for (int i = r0; i < r1; i++) {
        int s = g_esrc[i];
        float4 sv = *(const float4*)(g_out1 + (size_t)s * HIDD + lane * 4);
        acc.x += elu(sv.x * sc.x + sh.x);
        acc.y += elu(sv.y * sc.y + sh.y);
        acc.z += elu(sv.z * sc.z + sh.z);
        acc.w += elu(sv.w * sc.w + sh.w);
    }
    uint32_t h0, l0, h1w, l1;
    hiLo(acc.x, acc.y, h0, l0);
    hiLo(acc.z, acc.w, h1w, l1);
    size_t base = (size_t)d * 64 + lane * 2;
    g_zhi[base] = h0; g_zhi[base + 1] = h1w;
    g_zlo[base] = l0; g_zlo[base + 1] = l1;
}

// ---------------- batch norm finalize / apply ----------------
__global__ void k_bn_final(const float* __restrict__ gamma, const float* __restrict__ beta) {
    int c = threadIdx.x;
    float mean = g_sum[c] / (float)NN;
    float var  = g_sumsq[c] / (float)NN - mean * mean;
    float sc   = gamma[c] * rsqrtf(var + BN_EPS);
    g_scale[c] = sc;
    g_shift[c] = beta[c] - mean * sc;
    g_sum[c] = 0.f;
    g_sumsq[c] = 0.f;
}

// final output: Xext -> Yext (in place), BN2 scale/shift + ELU
__global__ void k_bn_apply_elu(const float* __restrict__ Xext, float* __restrict__ Yext) {
    size_t i = (size_t)blockIdx.x * blockDim.x + threadIdx.x;
    int c4 = (int)(i & 31);
    float4 v  = ((const float4*)Xext)[i];
    float4 sc = ((const float4*)g_scale)[c4];
    float4 sh = ((const float4*)g_shift)[c4];
    float4 o;
    o.x = elu(v.x * sc.x + sh.x);
    o.y = elu(v.y * sc.y + sh.y);
    o.z = elu(v.z * sc.z + sh.z);
    o.w = elu(v.w * sc.w + sh.w);
    ((float4*)Yext)[i] = o;
}

// ---------------- launch ----------------
extern "C" void kernel_launch(void* const* d_in, const int* in_sizes, int n_in,
                              void* d_out, int out_size) {
    const float* x         = (const float*)d_in[0];
    const float* W_gat     = (const float*)d_in[1];
    const float* att_src   = (const float*)d_in[2];
    const float* att_dst   = (const float*)d_in[3];
    const float* bn1_gamma = (const float*)d_in[5];
    const float* bn1_beta  = (const float*)d_in[6];
    const float* eps_gin   = (const float*)d_in[7];
    const float* lin_W     = (const float*)d_in[8];
    const float* bn2_gamma = (const float*)d_in[10];
    const float* bn2_beta  = (const float*)d_in[11];
    const void*  edge_idx  = d_in[12];
    float* out = (float*)d_out;

    static cudaStream_t s2 = nullptr;
    static cudaEvent_t evFork = nullptr, evJoin = nullptr;
    if (!s2) {
        cudaStreamCreateWithFlags(&s2, cudaStreamNonBlocking);
        cudaEventCreateWithFlags(&evFork, cudaEventDisableTiming);
        cudaEventCreateWithFlags(&evJoin, cudaEventDisableTiming);
    }

    // fork: GEMM1 chain on s2, CSR chain on stream 0
    cudaEventRecord(evFork, 0);
    cudaStreamWaitEvent(s2, evFork, 0);

    // --- s2: weight conversion + GEMM1 (+ att epilogue) ---
    k_cvtW<<<(INC * 64 + HIDD * 64 + 255) / 256, 256, 0, s2>>>(W_gat, lin_W);
    k_gemm1<<<(NN + 127) / 128, 256, 0, s2>>>(x, att_src, att_dst);
    cudaEventRecord(evJoin, s2);

    // --- stream 0: init + CSR build (independent of GEMM1) ---
    k_init<<<(NN + 255) / 256, 256>>>();
    k_detect<<<1, 256>>>((const long long*)edge_idx);
    k_edgecvt<<<NE / 256, 256>>>(edge_idx);
    k_scan1<<<NBLK, SCANB>>>();
    k_scan2<<<1, 128>>>();
    k_scan3<<<(NN + 255) / 256, 256>>>();
    k_scatter<<<NE / 256, 256>>>();

    // join: GAT needs g_h/g_asrc/g_adst (s2) + CSR + g_sum zeros (stream 0)
    cudaStreamWaitEvent(0, evJoin, 0);

    // GAT two-pass softmax + aggregation + BN1 stats
    k_gat_csr<<<(NN * 32 + 255) / 256, 256>>>();

    // BN1 finalize (scale/shift for fused GIN)
    k_bn_final<<<1, 128>>>(bn1_gamma, bn1_beta);

    // GIN aggregation with fused BN1-apply+ELU, emit bf16 hi/lo z
    k_gin_z<<<(NN * 32 + 255) / 256, 256>>>(eps_gin);

    // GEMM2 (bf16x3 tensor) -> out, + BN2 stats
    k_gemm2<<<(NN + 127) / 128, 256>>>(out);

    // BN2 finalize + apply in place
    k_bn_final<<<1, 128>>>(bn2_gamma, bn2_beta);
    k_bn_apply_elu<<<(NN * HIDD / 4) / 256, 256>>>(out, out);
}

// round 14
// speedup vs baseline: 1.5390x; 1.5390x over previous
#include <cuda_runtime.h>
#include <math.h>
#include <stdint.h>

#define NN   100000
#define NE   1600000
#define INC  256
#define HIDD 128
#define HEADS 4
#define CHEAD 32
#define BN_EPS 1e-5f
#define NEG_SLOPE 0.2f
#define SCANB 1024
#define NBLK  ((NN + SCANB - 1) / SCANB)   // 98

// ---------------- scratch (device globals: no allocs allowed) ----------------
__device__ float    g_h   [(size_t)NN*HIDD];   // x @ W_gat
__device__ float    g_h1  [(size_t)NN*HIDD];   // post BN1+ELU
__device__ float    g_out1[(size_t)NN*HIDD];   // GAT aggregation (pre BN1)
__device__ uint32_t g_zhi [(size_t)NN*64];     // z=(1+eps)h1+agg, bf16 hi pairs
__device__ uint32_t g_zlo [(size_t)NN*64];     // bf16 lo pairs
__device__ uint32_t g_B1hi[INC*64],  g_B1lo[INC*64];    // W_gat bf16 col-pairs
__device__ uint32_t g_B2hi[HIDD*64], g_B2lo[HIDD*64];   // lin_W
__device__ float g_asrc[NN*HEADS];
__device__ float g_adst[NN*HEADS];
__device__ float g_sum [HIDD];
__device__ float g_sumsq[HIDD];
__device__ float g_scale[HIDD];
__device__ float g_shift[HIDD];
__device__ int   g_src[NE];
__device__ int   g_dst[NE];
__device__ int   g_esrc[NE];                // CSR: src ids grouped by dst
__device__ int   g_rowptr[NN+1];
__device__ int   g_deg[NN];
__device__ int   g_woff[NN];
__device__ int   g_bsum[NBLK];
__device__ int   g_boff[NBLK];
__device__ int   g_is64;

// ---------------- helpers ----------------
__device__ __forceinline__ void redAdd1(float* addr, float v) {
    asm volatile("red.global.add.f32 [%0], %1;" :: "l"(addr), "f"(v) : "memory");
}
__device__ __forceinline__ float lrelu(float x) { return x > 0.0f ? x : NEG_SLOPE * x; }
__device__ __forceinline__ float elu(float x)   { return x > 0.0f ? x : expm1f(x); }

__device__ __forceinline__ uint32_t bf16pack(float x1, float x0) {
    uint32_t r;
    asm("cvt.rn.bf16x2.f32 %0, %1, %2;" : "=r"(r) : "f"(x1), "f"(x0));
    return r;
}
__device__ __forceinline__ void hiLo(float x0, float x1, uint32_t& h, uint32_t& l) {
    h = bf16pack(x1, x0);
    float r0 = x0 - __uint_as_float(h << 16);
    float r1 = x1 - __uint_as_float(h & 0xffff0000u);
    l = bf16pack(r1, r0);
}

#define LDM_X4(r, addr)                                                        \
    asm volatile("ldmatrix.sync.aligned.m8n8.x4.shared.b16 {%0,%1,%2,%3}, [%4];" \
        : "=r"((r)[0]), "=r"((r)[1]), "=r"((r)[2]), "=r"((r)[3]) : "r"(addr))
#define LDM_X4T(r, addr)                                                       \
    asm volatile("ldmatrix.sync.aligned.m8n8.x4.trans.shared.b16 {%0,%1,%2,%3}, [%4];" \
        : "=r"((r)[0]), "=r"((r)[1]), "=r"((r)[2]), "=r"((r)[3]) : "r"(addr))
#define MMA16(d, a, b0, b1)                                                    \
    asm volatile("mma.sync.aligned.m16n8k16.row.col.f32.bf16.bf16.f32 "        \
        "{%0,%1,%2,%3}, {%4,%5,%6,%7}, {%8,%9}, {%0,%1,%2,%3};"                \
        : "+f"((d)[0]), "+f"((d)[1]), "+f"((d)[2]), "+f"((d)[3])               \
        : "r"((a)[0]), "r"((a)[1]), "r"((a)[2]), "r"((a)[3]), "r"(b0), "r"(b1))

// ---------------- init ----------------
__global__ void k_init() {
    int i = blockIdx.x * blockDim.x + threadIdx.x;
    if (i < NN) { g_deg[i] = 0; g_woff[i] = 0; }
    if (i < HIDD) { g_sum[i] = 0.0f; g_sumsq[i] = 0.0f; }
}

__global__ void k_detect(const long long* __restrict__ ei) {
    __shared__ int ok;
    if (threadIdx.x == 0) ok = 1;
    __syncthreads();
    for (int i = threadIdx.x; i < 1024; i += blockDim.x) {
        long long v = ei[i];
        if (v < 0 || v >= NN) atomicExch(&ok, 0);
    }
    __syncthreads();
    if (threadIdx.x == 0) g_is64 = ok;
}

__global__ void k_edgecvt(const void* __restrict__ eiv) {
    int i = blockIdx.x * blockDim.x + threadIdx.x;
    if (i >= NE) return;
    int s, d;
    if (g_is64) {
        const long long* p = (const long long*)eiv;
        s = (int)p[i]; d = (int)p[NE + i];
    } else {
        const int* p = (const int*)eiv;
        s = p[i]; d = p[NE + i];
    }
    g_src[i] = s;
    g_dst[i] = d;
    atomicAdd(&g_deg[d], 1);
}

// ---------------- prefix scan ----------------
__global__ void k_scan1() {
    __shared__ int sh[SCANB];
    int tid = threadIdx.x;
    int i = blockIdx.x * SCANB + tid;
    int v = (i < NN) ? g_deg[i] : 0;
    sh[tid] = v;
    __syncthreads();
    for (int off = 1; off < SCANB; off <<= 1) {
        int t = (tid >= off) ? sh[tid - off] : 0;
        __syncthreads();
        sh[tid] += t;
        __syncthreads();
    }
    if (i < NN) g_rowptr[i + 1] = sh[tid];
    if (tid == SCANB - 1) g_bsum[blockIdx.x] = sh[tid];
}

// 128-thread shfl scan over NBLK block sums -> exclusive offsets
__global__ void k_scan2() {
    __shared__ int wsum[4];
    int t = threadIdx.x, lane = t & 31, w = t >> 5;
    int v = (t < NBLK) ? g_bsum[t] : 0;
    int x = v;
#pragma unroll
    for (int off = 1; off < 32; off <<= 1) {
        int y = __shfl_up_sync(0xffffffffu, x, off);
        if (lane >= off) x += y;
    }
    if (lane == 31) wsum[w] = x;
    __syncthreads();
    int wpre = 0;
#pragma unroll
    for (int k = 0; k < 4; k++) if (k < w) wpre += wsum[k];
    if (t < NBLK) g_boff[t] = wpre + x - v;   // exclusive
}

__global__ void k_scan3() {
    int i = blockIdx.x * blockDim.x + threadIdx.x;
    if (i == 0) g_rowptr[0] = 0;
    if (i < NN) g_rowptr[i + 1] += g_boff[i >> 10];
}
__global__ void k_scatter() {
    int e = blockIdx.x * blockDim.x + threadIdx.x;
    if (e >= NE) return;
    int d = g_dst[e];
    int pos = g_rowptr[d] + atomicAdd(&g_woff[d], 1);
    g_esrc[pos] = g_src[e];
}

// ---------------- preconvert weights to bf16 hi/lo (col-pair packed) --------
__global__ void k_cvtW(const float* __restrict__ Wg, const float* __restrict__ Wl) {
    int i = blockIdx.x * blockDim.x + threadIdx.x;
    if (i < INC * 64) {
        float2 v = *(const float2*)(Wg + (size_t)i * 2);
        uint32_t h, l; hiLo(v.x, v.y, h, l);
        g_B1hi[i] = h; g_B1lo[i] = l;
    } else if (i < INC * 64 + HIDD * 64) {
        int j = i - INC * 64;
        float2 v = *(const float2*)(Wl + (size_t)j * 2);
        uint32_t h, l; hiLo(v.x, v.y, h, l);
        g_B2hi[j] = h; g_B2lo[j] = l;
    }
}

// -------- GEMM1: g_h = x @ W_gat (bf16x3) + attention logits epilogue -------
__global__ __launch_bounds__(256, 2) void k_gemm1(
    const float* __restrict__ A,
    const float* __restrict__ att_s, const float* __restrict__ att_d)
{
    __shared__ uint32_t sAhi[128][20], sAlo[128][20];
    __shared__ uint32_t sBhi[32][68],  sBlo[32][68];
    __shared__ float    sAS[128][4],   sAD[128][4];

    int t = threadIdx.x, lane = t & 31, wid = t >> 5;
    int g = lane >> 2, tq = lane & 3;
    int wm = wid >> 1, wn = wid & 1;
    int blockM = blockIdx.x * 128;

    if (t < 128) {
#pragma unroll
        for (int hd = 0; hd < 4; hd++) { sAS[t][hd] = 0.f; sAD[t][hd] = 0.f; }
    }

    unsigned aHiB = (unsigned)__cvta_generic_to_shared(&sAhi[0][0]);
    unsigned aLoB = (unsigned)__cvta_generic_to_shared(&sAlo[0][0]);
    unsigned bHiB = (unsigned)__cvta_generic_to_shared(&sBhi[0][0]);
    unsigned bLoB = (unsigned)__cvta_generic_to_shared(&sBlo[0][0]);

    int la_row = (lane & 7) + 8 * ((lane >> 3) & 1);
    int la_k   = ((lane >> 4) & 1) * 4;
    int lb_k   = (lane & 7) + 8 * ((lane >> 3) & 1);
    int lb_c   = ((lane >> 4) & 1) * 4;

    float acc[2][8][4];
#pragma unroll
    for (int m = 0; m < 2; m++)
#pragma unroll
        for (int j = 0; j < 8; j++)
#pragma unroll
            for (int c = 0; c < 4; c++) acc[m][j][c] = 0.0f;

    for (int kt = 0; kt < INC / 32; kt++) {
#pragma unroll
        for (int i = 0; i < 4; i++) {
            int li  = i * 256 + t;
            int row = li >> 3, kidx = li & 7;
            int grow = blockM + row;
            float4 v = make_float4(0.f, 0.f, 0.f, 0.f);
            if (grow < NN)
                v = *(const float4*)(A + (size_t)grow * INC + kt * 32 + kidx * 4);
            uint32_t h0, l0, h1, l1;
            hiLo(v.x, v.y, h0, l0);
            hiLo(v.z, v.w, h1, l1);
            sAhi[row][kidx * 2] = h0; sAhi[row][kidx * 2 + 1] = h1;
            sAlo[row][kidx * 2] = l0; sAlo[row][kidx * 2 + 1] = l1;
        }
#pragma unroll
        for (int i = 0; i < 2; i++) {
            int li = i * 256 + t;
            int k  = li >> 4, c4 = (li & 15) * 4;
            size_t gi = (size_t)(kt * 32 + k) * 64 + c4;
            *(uint4*)&sBhi[k][c4] = *(const uint4*)(g_B1hi + gi);
            *(uint4*)&sBlo[k][c4] = *(const uint4*)(g_B1lo + gi);
        }
        __syncthreads();

#pragma unroll
        for (int ks = 0; ks < 2; ks++) {
            int Kw = ks * 8;
            uint32_t ahi[2][4], alo[2][4];
#pragma unroll
            for (int m = 0; m < 2; m++) {
                int R0 = wm * 32 + m * 16;
                unsigned off = ((R0 + la_row) * 20 + Kw + la_k) * 4;
                LDM_X4(ahi[m], aHiB + off);
                LDM_X4(alo[m], aLoB + off);
            }
#pragma unroll
            for (int jj = 0; jj < 4; jj++) {
                int C0 = wn * 64 + jj * 16;
                unsigned off = ((ks * 16 + lb_k) * 68 + C0 / 2 + lb_c) * 4;
                uint32_t bh[4], bl[4];
                LDM_X4T(bh, bHiB + off);
                LDM_X4T(bl, bLoB + off);
#pragma unroll
                for (int m = 0; m < 2; m++) {
                    MMA16(acc[m][2 * jj],     ahi[m], bh[0], bh[1]);
                    MMA16(acc[m][2 * jj],     ahi[m], bl[0], bl[1]);
                    MMA16(acc[m][2 * jj],     alo[m], bh[0], bh[1]);
                    MMA16(acc[m][2 * jj + 1], ahi[m], bh[2], bh[3]);
                    MMA16(acc[m][2 * jj + 1], ahi[m], bl[2], bl[3]);
                    MMA16(acc[m][2 * jj + 1], alo[m], bh[2], bh[3]);
                }
            }
        }
        __syncthreads();
    }

    float ps[4][2], pd[4][2];
#pragma unroll
    for (int r = 0; r < 4; r++) { ps[r][0] = ps[r][1] = 0.f; pd[r][0] = pd[r][1] = 0.f; }

#pragma unroll
    for (int m = 0; m < 2; m++) {
#pragma unroll
        for (int j = 0; j < 8; j++) {
            int row = blockM + wm * 32 + m * 16 + g;
            int col = wn * 64 + j * 8 + tq * 2;
            if (row < NN)
                *(float2*)(g_h + (size_t)row * HIDD + col) =
                    make_float2(acc[m][j][0], acc[m][j][1]);
            if (row + 8 < NN)
                *(float2*)(g_h + (size_t)(row + 8) * HIDD + col) =
                    make_float2(acc[m][j][2], acc[m][j][3]);
            float as0 = __ldg(att_s + col), as1 = __ldg(att_s + col + 1);
            float ad0 = __ldg(att_d + col), ad1 = __ldg(att_d + col + 1);
            int hh = j >> 2;
            ps[m * 2 + 0][hh] += acc[m][j][0] * as0 + acc[m][j][1] * as1;
            pd[m * 2 + 0][hh] += acc[m][j][0] * ad0 + acc[m][j][1] * ad1;
            ps[m * 2 + 1][hh] += acc[m][j][2] * as0 + acc[m][j][3] * as1;
            pd[m * 2 + 1][hh] += acc[m][j][2] * ad0 + acc[m][j][3] * ad1;
        }
    }
#pragma unroll
    for (int m = 0; m < 2; m++) {
#pragma unroll
        for (int r = 0; r < 2; r++) {
            int rloc = wm * 32 + m * 16 + g + r * 8;
#pragma unroll
            for (int hh = 0; hh < 2; hh++) {
                atomicAdd(&sAS[rloc][wn * 2 + hh], ps[m * 2 + r][hh]);
                atomicAdd(&sAD[rloc][wn * 2 + hh], pd[m * 2 + r][hh]);
            }
        }
    }
    __syncthreads();
    if (t < 128) {
        int row = blockM + t;
        if (row < NN) {
            *(float4*)(g_asrc + row * 4) = *(const float4*)&sAS[t][0];
            *(float4*)(g_adst + row * 4) = *(const float4*)&sAD[t][0];
        }
    }
}

// ---------------- GEMM2: out = z @ lin_W, + BN2 stats (bf16x3) --------------
__global__ __launch_bounds__(256, 2) void k_gemm2(float* __restrict__ C) {
    __shared__ uint32_t sAhi[128][20], sAlo[128][20];
    __shared__ uint32_t sBhi[32][68],  sBlo[32][68];

    int t = threadIdx.x, lane = t & 31, wid = t >> 5;
    int g = lane >> 2, tq = lane & 3;
    int wm = wid >> 1, wn = wid & 1;
    int blockM = blockIdx.x * 128;

    unsigned aHiB = (unsigned)__cvta_generic_to_shared(&sAhi[0][0]);
    unsigned aLoB = (unsigned)__cvta_generic_to_shared(&sAlo[0][0]);
    unsigned bHiB = (unsigned)__cvta_generic_to_shared(&sBhi[0][0]);
    unsigned bLoB = (unsigned)__cvta_generic_to_shared(&sBlo[0][0]);

    int la_row = (lane & 7) + 8 * ((lane >> 3) & 1);
    int la_k   = ((lane >> 4) & 1) * 4;
    int lb_k   = (lane & 7) + 8 * ((lane >> 3) & 1);
    int lb_c   = ((lane >> 4) & 1) * 4;

    float acc[2][8][4];
#pragma unroll
    for (int m = 0; m < 2; m++)
#pragma unroll
        for (int j = 0; j < 8; j++)
#pragma unroll
            for (int c = 0; c < 4; c++) acc[m][j][c] = 0.0f;

    for (int kt = 0; kt < HIDD / 32; kt++) {
#pragma unroll
        for (int i = 0; i < 2; i++) {
            int li  = i * 256 + t;
            int row = li >> 2, wq = (li & 3) * 4;
            int grow = blockM + row;
            uint4 vh = make_uint4(0, 0, 0, 0), vl = make_uint4(0, 0, 0, 0);
            if (grow < NN) {
                size_t gi = (size_t)grow * 64 + kt * 16 + wq;
                vh = *(const uint4*)(g_zhi + gi);
                vl = *(const uint4*)(g_zlo + gi);
            }
            *(uint4*)&sAhi[row][wq] = vh;
            *(uint4*)&sAlo[row][wq] = vl;
        }
#pragma unroll
        for (int i = 0; i < 2; i++) {
            int li = i * 256 + t;
            int k  = li >> 4, c4 = (li & 15) * 4;
            size_t gi = (size_t)(kt * 32 + k) * 64 + c4;
            *(uint4*)&sBhi[k][c4] = *(const uint4*)(g_B2hi + gi);
            *(uint4*)&sBlo[k][c4] = *(const uint4*)(g_B2lo + gi);
        }
        __syncthreads();

#pragma unroll
        for (int ks = 0; ks < 2; ks++) {
            int Kw = ks * 8;
            uint32_t ahi[2][4], alo[2][4];
#pragma unroll
            for (int m = 0; m < 2; m++) {
                int R0 = wm * 32 + m * 16;
                unsigned off = ((R0 + la_row) * 20 + Kw + la_k) * 4;
                LDM_X4(ahi[m], aHiB + off);
                LDM_X4(alo[m], aLoB + off);
            }
#pragma unroll
            for (int jj = 0; jj < 4; jj++) {
                int C0 = wn * 64 + jj * 16;
                unsigned off = ((ks * 16 + lb_k) * 68 + C0 / 2 + lb_c) * 4;
                uint32_t bh[4], bl[4];
                LDM_X4T(bh, bHiB + off);
                LDM_X4T(bl, bLoB + off);
#pragma unroll
                for (int m = 0; m < 2; m++) {
                    MMA16(acc[m][2 * jj],     ahi[m], bh[0], bh[1]);
                    MMA16(acc[m][2 * jj],     ahi[m], bl[0], bl[1]);
                    MMA16(acc[m][2 * jj],     alo[m], bh[0], bh[1]);
                    MMA16(acc[m][2 * jj + 1], ahi[m], bh[2], bh[3]);
                    MMA16(acc[m][2 * jj + 1], ahi[m], bl[2], bl[3]);
                    MMA16(acc[m][2 * jj + 1], alo[m], bh[2], bh[3]);
                }
            }
        }
        __syncthreads();
    }

#pragma unroll
    for (int m = 0; m < 2; m++) {
#pragma unroll
        for (int j = 0; j < 8; j++) {
            int row = blockM + wm * 32 + m * 16 + g;
            int col = wn * 64 + j * 8 + tq * 2;
            if (row < NN)
                *(float2*)(C + (size_t)row * HIDD + col) =
                    make_float2(acc[m][j][0], acc[m][j][1]);
            if (row + 8 < NN)
                *(float2*)(C + (size_t)(row + 8) * HIDD + col) =
                    make_float2(acc[m][j][2], acc[m][j][3]);
        }
    }

#pragma unroll
    for (int j = 0; j < 8; j++) {
        float s0 = 0.f, q0 = 0.f, s1 = 0.f, q1 = 0.f;
#pragma unroll
        for (int m = 0; m < 2; m++) {
            float v0 = acc[m][j][0], v1 = acc[m][j][1];
            float v2 = acc[m][j][2], v3 = acc[m][j][3];
            s0 += v0 + v2; q0 += v0 * v0 + v2 * v2;
            s1 += v1 + v3; q1 += v1 * v1 + v3 * v3;
        }
#pragma unroll
        for (int off = 4; off < 32; off <<= 1) {
            s0 += __shfl_xor_sync(0xffffffffu, s0, off);
            q0 += __shfl_xor_sync(0xffffffffu, q0, off);
            s1 += __shfl_xor_sync(0xffffffffu, s1, off);
            q1 += __shfl_xor_sync(0xffffffffu, q1, off);
        }
        if (g == 0) {
            int cn = wn * 64 + j * 8 + tq * 2;
            redAdd1(g_sum + cn, s0);     redAdd1(g_sumsq + cn, q0);
            redAdd1(g_sum + cn + 1, s1); redAdd1(g_sumsq + cn + 1, q1);
        }
    }
}

// -------- GAT fused softmax+aggregate (warp/dst) + smem BN1 stats -----------
__global__ __launch_bounds__(256) void k_gat_csr() {
    __shared__ float ssum[HIDD], ssq[HIDD];
    int t = threadIdx.x;
    if (t < HIDD) { ssum[t] = 0.f; ssq[t] = 0.f; }
    __syncthreads();

    int gw   = (blockIdx.x * blockDim.x + t) >> 5;
    int lane = t & 31;
    float4 acc = make_float4(0.f, 0.f, 0.f, 0.f);

    if (gw < NN) {
        int d  = gw;
        int r0 = g_rowptr[d], r1 = g_rowptr[d + 1];
        if (r0 < r1) {
            float4 ad = *(const float4*)(g_adst + d * 4);
            float4 m = make_float4(-INFINITY, -INFINITY, -INFINITY, -INFINITY);
            for (int i = r0 + lane; i < r1; i += 32) {
                int s = g_esrc[i];
                float4 a = *(const float4*)(g_asrc + s * 4);
                m.x = fmaxf(m.x, lrelu(a.x + ad.x));
                m.y = fmaxf(m.y, lrelu(a.y + ad.y));
                m.z = fmaxf(m.z, lrelu(a.z + ad.z));
                m.w = fmaxf(m.w, lrelu(a.w + ad.w));
            }
#pragma unroll
            for (int off = 16; off; off >>= 1) {
                m.x = fmaxf(m.x, __shfl_xor_sync(0xffffffffu, m.x, off));
                m.y = fmaxf(m.y, __shfl_xor_sync(0xffffffffu, m.y, off));
                m.z = fmaxf(m.z, __shfl_xor_sync(0xffffffffu, m.z, off));
                m.w = fmaxf(m.w, __shfl_xor_sync(0xffffffffu, m.w, off));
            }
            int head = lane >> 3;
            float mh  = (head == 0) ? m.x  : (head == 1) ? m.y  : (head == 2) ? m.z  : m.w;
            float adh = (head == 0) ? ad.x : (head == 1) ? ad.y : (head == 2) ? ad.z : ad.w;
            float den = 0.f;
            for (int i = r0; i < r1; i++) {
                int s = g_esrc[i];
                float ah = __ldg(g_asrc + s * 4 + head);
                float num = __expf(lrelu(ah + adh) - mh);
                den += num;
                float4 hv = *(const float4*)(g_h + (size_t)s * HIDD + lane * 4);
                acc.x += num * hv.x; acc.y += num * hv.y;
                acc.z += num * hv.z; acc.w += num * hv.w;
            }
            float inv = 1.0f / den;
            acc.x *= inv; acc.y *= inv; acc.z *= inv; acc.w *= inv;
        }
        *(float4*)(g_out1 + (size_t)gw * HIDD + lane * 4) = acc;
        atomicAdd(&ssum[lane * 4 + 0], acc.x); atomicAdd(&ssq[lane * 4 + 0], acc.x * acc.x);
        atomicAdd(&ssum[lane * 4 + 1], acc.y); atomicAdd(&ssq[lane * 4 + 1], acc.y * acc.y);
        atomicAdd(&ssum[lane * 4 + 2], acc.z); atomicAdd(&ssq[lane * 4 + 2], acc.z * acc.z);
        atomicAdd(&ssum[lane * 4 + 3], acc.w); atomicAdd(&ssq[lane * 4 + 3], acc.w * acc.w);
    }
    __syncthreads();
    if (t < HIDD) {
        redAdd1(g_sum + t, ssum[t]);
        redAdd1(g_sumsq + t, ssq[t]);
    }
}

// -------- GIN: z = (1+eps)*h1[d] + sum h1[src], emit bf16 hi/lo -------------
__global__ __launch_bounds__(256) void k_gin_z(const float* __restrict__ epsPtr) {
    int gw   = (blockIdx.x * blockDim.x + threadIdx.x) >> 5;
    int lane = threadIdx.x & 31;
    if (gw >= NN) return;
    int d  = gw;
    int r0 = g_rowptr[d], r1 = g_rowptr[d + 1];
    float ke = 1.0f + __ldg(epsPtr);
    float4 hv = *(const float4*)(g_h1 + (size_t)d * HIDD + lane * 4);
    float4 acc = make_float4(ke * hv.x, ke * hv.y, ke * hv.z, ke * hv.w);
    for (int i = r0; i < r1; i++) {
        int s = g_esrc[i];
        float4 sv = *(const float4*)(g_h1 + (size_t)s * HIDD + lane * 4);
        acc.x += sv.x; acc.y += sv.y; acc.z += sv.z; acc.w += sv.w;
    }
    uint32_t h0, l0, h1w, l1;
    hiLo(acc.x, acc.y, h0, l0);
    hiLo(acc.z, acc.w, h1w, l1);
    size_t base = (size_t)d * 64 + lane * 2;
    g_zhi[base] = h0; g_zhi[base + 1] = h1w;
    g_zlo[base] = l0; g_zlo[base + 1] = l1;
}

// ---------------- batch norm finalize / apply ----------------
__global__ void k_bn_final(const float* __restrict__ gamma, const float* __restrict__ beta) {
    int c = threadIdx.x;
    float mean = g_sum[c] / (float)NN;
    float var  = g_sumsq[c] / (float)NN - mean * mean;
    float sc   = gamma[c] * rsqrtf(var + BN_EPS);
    g_scale[c] = sc;
    g_shift[c] = beta[c] - mean * sc;
    g_sum[c] = 0.f;
    g_sumsq[c] = 0.f;
}

__global__ void k_bn_apply_elu(const float* __restrict__ Xext, float* __restrict__ Yext, int mode) {
    const float* X = (mode == 0) ? g_out1 : Xext;
    float*       Y = (mode == 0) ? g_h1   : Yext;
    size_t i = (size_t)blockIdx.x * blockDim.x + threadIdx.x;
    int c4 = (int)(i & 31);
    float4 v  = ((const float4*)X)[i];
    float4 sc = ((const float4*)g_scale)[c4];
    float4 sh = ((const float4*)g_shift)[c4];
    float4 o;
    o.x = elu(v.x * sc.x + sh.x);
    o.y = elu(v.y * sc.y + sh.y);
    o.z = elu(v.z * sc.z + sh.z);
    o.w = elu(v.w * sc.w + sh.w);
    ((float4*)Y)[i] = o;
}

// ---------------- launch ----------------
extern "C" void kernel_launch(void* const* d_in, const int* in_sizes, int n_in,
                              void* d_out, int out_size) {
    const float* x         = (const float*)d_in[0];
    const float* W_gat     = (const float*)d_in[1];
    const float* att_src   = (const float*)d_in[2];
    const float* att_dst   = (const float*)d_in[3];
    const float* bn1_gamma = (const float*)d_in[5];
    const float* bn1_beta  = (const float*)d_in[6];
    const float* eps_gin   = (const float*)d_in[7];
    const float* lin_W     = (const float*)d_in[8];
    const float* bn2_gamma = (const float*)d_in[10];
    const float* bn2_beta  = (const float*)d_in[11];
    const void*  edge_idx  = d_in[12];
    float* out = (float*)d_out;

    static cudaStream_t s2 = nullptr;
    static cudaEvent_t evFork = nullptr, evJoin = nullptr;
    if (!s2) {
        cudaStreamCreateWithFlags(&s2, cudaStreamNonBlocking);
        cudaEventCreateWithFlags(&evFork, cudaEventDisableTiming);
        cudaEventCreateWithFlags(&evJoin, cudaEventDisableTiming);
    }

    // fork: GEMM1 chain on s2, CSR chain on stream 0
    cudaEventRecord(evFork, 0);
    cudaStreamWaitEvent(s2, evFork, 0);

    // --- s2: weight conversion + GEMM1 (+ att epilogue) ---
    k_cvtW<<<(INC * 64 + HIDD * 64 + 255) / 256, 256, 0, s2>>>(W_gat, lin_W);
    k_gemm1<<<(NN + 127) / 128, 256, 0, s2>>>(x, att_src, att_dst);
    cudaEventRecord(evJoin, s2);

    // --- stream 0: init + CSR build (independent of GEMM1) ---
    k_init<<<(NN + 255) / 256, 256>>>();
    k_detect<<<1, 256>>>((const long long*)edge_idx);
    k_edgecvt<<<NE / 256, 256>>>(edge_idx);
    k_scan1<<<NBLK, SCANB>>>();
    k_scan2<<<1, 128>>>();
    k_scan3<<<(NN + 255) / 256, 256>>>();
    k_scatter<<<NE / 256, 256>>>();

    // join: GAT needs g_h/g_asrc/g_adst (s2) + CSR + g_sum zeros (stream 0)
    cudaStreamWaitEvent(0, evJoin, 0);

    // GAT two-pass softmax + aggregation + BN1 stats
    k_gat_csr<<<(NN * 32 + 255) / 256, 256>>>();

    // BN1 finalize + apply -> g_h1
    k_bn_final<<<1, 128>>>(bn1_gamma, bn1_beta);
    k_bn_apply_elu<<<(NN * HIDD / 4) / 256, 256>>>(nullptr, nullptr, 0);

    // GIN aggregation + z emit (bf16 hi/lo)
    k_gin_z<<<(NN * 32 + 255) / 256, 256>>>(eps_gin);

    // GEMM2 (bf16x3 tensor) -> out, + BN2 stats
    k_gemm2<<<(NN + 127) / 128, 256>>>(out);

    // BN2 finalize + apply in place
    k_bn_final<<<1, 128>>>(bn2_gamma, bn2_beta);
    k_bn_apply_elu<<<(NN * HIDD / 4) / 256, 256>>>(out, out, 1);
}